// round 8
// baseline (speedup 1.0000x reference)
#include <cuda_runtime.h>
#include <cstdint>

// ---------------------------------------------------------------------------
// TensorTrain forward, right-to-left vector sweep, fp32x2 register-tiled GEMM.
//   v7[l,s]   = sum_p x[s,7,p] * core_last[l,p]          (state stored [l][s])
//   v_j[l,s]  = sum_{p,r} cores_mid[j][l,p,r] * x[s,j+1,p] * v_{j+1}[r,s]
//   out[s,c]  = sum_{p,r} core_first[c,p,r] * x[s,0,p] * v_0[r,s]
// R4 structure (KS=32, PC=2, single staging phase) but W stored UNduplicated
// ([p][r][l], stride 68) -> ~70KB smem/CTA -> 3 CTAs/SM (12 warps).
// In-loop dup2 packs W into f32x2 operands on the idle MOV/ALU pipe.
// ---------------------------------------------------------------------------

namespace {

constexpr int Bn = 4096;
constexpr int Nn = 8;
constexpr int Fn = 64;
constexpr int Dn = 64;
constexpr int Cn = 10;
constexpr int NMID = 6;

constexpr int KS = 32;       // split-K over p (mid kernel)
constexpr int PC = Fn / KS;  // 2 p per CTA
constexpr int KSF = 8;       // split-K over p (final kernel)
constexpr int PCF = Fn / KSF;

constexpr int VS = 132;      // smem row stride (floats) for v_t / x_t
constexpr int WST = 68;      // smem/global row stride for W tiles (16B aligned)

// dynamic smem layout (floats): v_t[64][VS] | ws[2][64][WST] | x_t[2][VS]
constexpr int SM_VT = 0;
constexpr int SM_WS = Dn * VS;                  // 8448
constexpr int SM_XT = SM_WS + PC * Dn * WST;    // 8448 + 8704
constexpr int SM_MID_BYTES = (SM_XT + PC * VS) * 4;  // ~69.8 KB

// device scratch (no allocations allowed)
__device__ float g_v[Dn * Bn];                       // 1 MB chain state, [l][s]
__device__ float g_part[(size_t)KS * Bn * Dn];       // 32 MB split-K partials
__device__ float g_w[(size_t)NMID * Fn * Dn * WST];  // 6.7 MB rearranged W

typedef unsigned long long ull;

__device__ __forceinline__ ull dup2(float a) {
  ull r; asm("mov.b64 %0, {%1, %1};" : "=l"(r) : "f"(a)); return r;
}
__device__ __forceinline__ void unpack2(ull v, float& a, float& b) {
  asm("mov.b64 {%0, %1}, %2;" : "=f"(a), "=f"(b) : "l"(v));
}
__device__ __forceinline__ ull ffma2(ull a, ull b, ull c) {
  ull d; asm("fma.rn.f32x2 %0, %1, %2, %3;" : "=l"(d) : "l"(a), "l"(b), "l"(c));
  return d;
}
__device__ __forceinline__ ull fmul2(ull a, ull b) {
  ull d; asm("mul.rn.f32x2 %0, %1, %2;" : "=l"(d) : "l"(a), "l"(b));
  return d;
}

// ---------------------------------------------------------------------------
// Pre-rearrange mid cores: g_w[j][p][r][l(+pad)] = cmid[j][l][p][r].
// One block per (j,p): 256 threads, stage [l][r] slab then write [r][l].
// ---------------------------------------------------------------------------
__global__ __launch_bounds__(256) void preconv_w_kernel(const float* __restrict__ cmid) {
  __shared__ float tmp[Dn * 68];  // [l][r], stride 68
  const int t = threadIdx.x;
  const int p = blockIdx.x & 63;
  const int j = blockIdx.x >> 6;

#pragma unroll
  for (int it = 0; it < (Dn * Dn) / 256; ++it) {
    int idx = it * 256 + t;
    int r = idx & 63;
    int l = idx >> 6;
    tmp[l * 68 + r] = cmid[(((size_t)j * Dn + l) * Fn + p) * Dn + r];
  }
  __syncthreads();

  float* out = g_w + ((size_t)j * Fn + p) * (Dn * WST);
#pragma unroll
  for (int it = 0; it < (Dn * Dn) / 256; ++it) {
    int idx = it * 256 + t;
    int l = idx & 63;
    int r = idx >> 6;
    out[r * WST + l] = tmp[l * 68 + r];
  }
}

// ---------------------------------------------------------------------------
// init: g_v[l][s] = sum_p x[s,7,p] * core_last[l,p]
// ---------------------------------------------------------------------------
__global__ __launch_bounds__(256) void init_v_kernel(const float* __restrict__ x,
                                                     const float* __restrict__ clast) {
  __shared__ __align__(16) float cl[Fn * 68];  // [p][l]
  const int tid = threadIdx.x;
  const int sl = tid & 63;
  const int l0 = (tid >> 6) * 16;
  const int s = blockIdx.x * 64 + sl;

#pragma unroll
  for (int k = 0; k < (Dn * Fn) / 256; ++k) {
    int idx = k * 256 + tid;
    int p = idx & 63;
    int l = idx >> 6;
    cl[p * 68 + l] = clast[l * Fn + p];
  }
  float xv[Fn];
  {
    const float4* xp =
        reinterpret_cast<const float4*>(x + (size_t)s * (Nn * Fn) + 7 * Fn);
#pragma unroll
    for (int k = 0; k < Fn / 4; ++k) {
      float4 t = xp[k];
      xv[4 * k] = t.x; xv[4 * k + 1] = t.y; xv[4 * k + 2] = t.z; xv[4 * k + 3] = t.w;
    }
  }
  __syncthreads();

  ull acc[8];
#pragma unroll
  for (int q = 0; q < 8; ++q) acc[q] = 0ull;
#pragma unroll 8
  for (int p = 0; p < Fn; ++p) {
    ull t2 = dup2(xv[p]);
    const ulonglong2* rp = reinterpret_cast<const ulonglong2*>(&cl[p * 68 + l0]);
#pragma unroll
    for (int q = 0; q < 4; ++q) {
      ulonglong2 cc = rp[q];
      acc[2 * q]     = ffma2(cc.x, t2, acc[2 * q]);
      acc[2 * q + 1] = ffma2(cc.y, t2, acc[2 * q + 1]);
    }
  }
#pragma unroll
  for (int q = 0; q < 8; ++q) {
    float a, b;
    unpack2(acc[q], a, b);
    g_v[(size_t)(l0 + 2 * q) * Bn + s] = a;
    g_v[(size_t)(l0 + 2 * q + 1) * Bn + s] = b;
  }
}

// ---------------------------------------------------------------------------
// mid step: partial[ks][l][s] = sum_{p in chunk} sum_r W[l,p,r]*x[s,t,p]*v[r,s]
// grid (Bn/128, KS), 128 threads. Thread tile: 8 samples (4 pairs) x 8 l.
// r-outer / p-inner; single __syncthreads; W dup'd in registers per (r,p).
// ---------------------------------------------------------------------------
__global__ __launch_bounds__(128) void mid_step_kernel(const float* __restrict__ x,
                                                       int j, int tIdx) {
  extern __shared__ __align__(16) float sm[];
  float* v_t = sm + SM_VT;   // [r][s], stride VS
  float* ws  = sm + SM_WS;   // [p][r][l], stride WST
  float* x_t = sm + SM_XT;   // [p][s], stride VS

  const int tid = threadIdx.x;
  const int si = tid & 15;   // sample octet
  const int li = tid >> 4;   // l octet
  const int s0 = blockIdx.x * 128;
  const int pbase = blockIdx.y * PC;

  // stage ws (34.8KB straight copy of two rearranged 17.4KB tiles)
  {
    const float4* srcw = reinterpret_cast<const float4*>(
        g_w + ((size_t)j * Fn + pbase) * (Dn * WST));
    float4* dstw = reinterpret_cast<float4*>(ws);
#pragma unroll
    for (int it = 0; it < (PC * Dn * WST) / (4 * 128); ++it)
      dstw[it * 128 + tid] = srcw[it * 128 + tid];
  }
  // stage v_t: straight copy of g_v[r][s0..s0+127]
#pragma unroll
  for (int it = 0; it < 16; ++it) {
    int idx = it * 128 + tid;
    int c4 = idx & 31;
    int r = idx >> 5;
    float4 t = *reinterpret_cast<const float4*>(&g_v[(size_t)r * Bn + s0 + c4 * 4]);
    *reinterpret_cast<float4*>(&v_t[r * VS + c4 * 4]) = t;
  }
  // stage x_t[p][s]
  {
    float2 t = *reinterpret_cast<const float2*>(
        x + (size_t)(s0 + tid) * (Nn * Fn) + (size_t)tIdx * Fn + pbase);
    x_t[0 * VS + tid] = t.x;
    x_t[1 * VS + tid] = t.y;
  }
  __syncthreads();

  // x sample-pairs for both p (registers)
  ull xp0[4], xp1[4];
#pragma unroll
  for (int q = 0; q < 4; ++q) {
    xp0[q] = *reinterpret_cast<const ull*>(&x_t[0 * VS + si * 8 + 2 * q]);
    xp1[q] = *reinterpret_cast<const ull*>(&x_t[1 * VS + si * 8 + 2 * q]);
  }

  ull acc[4][8];
#pragma unroll
  for (int jj = 0; jj < 4; ++jj)
#pragma unroll
    for (int q = 0; q < 8; ++q) acc[jj][q] = 0ull;

#pragma unroll 4
  for (int r = 0; r < Dn; ++r) {
    const float* vrow = &v_t[r * VS + si * 8];
    ulonglong2 va = *reinterpret_cast<const ulonglong2*>(vrow);
    ulonglong2 vb = *reinterpret_cast<const ulonglong2*>(vrow + 4);

    // p = 0
    {
      ull a0 = fmul2(va.x, xp0[0]);
      ull a1 = fmul2(va.y, xp0[1]);
      ull a2 = fmul2(vb.x, xp0[2]);
      ull a3 = fmul2(vb.y, xp0[3]);
      const float* wrow = &ws[(0 * Dn + r) * WST + li * 8];
      float4 wA = *reinterpret_cast<const float4*>(wrow);
      float4 wB = *reinterpret_cast<const float4*>(wrow + 4);
      ull w0 = dup2(wA.x), w1 = dup2(wA.y), w2 = dup2(wA.z), w3 = dup2(wA.w);
      ull w4 = dup2(wB.x), w5 = dup2(wB.y), w6 = dup2(wB.z), w7 = dup2(wB.w);
      acc[0][0] = ffma2(a0, w0, acc[0][0]); acc[1][0] = ffma2(a1, w0, acc[1][0]);
      acc[2][0] = ffma2(a2, w0, acc[2][0]); acc[3][0] = ffma2(a3, w0, acc[3][0]);
      acc[0][1] = ffma2(a0, w1, acc[0][1]); acc[1][1] = ffma2(a1, w1, acc[1][1]);
      acc[2][1] = ffma2(a2, w1, acc[2][1]); acc[3][1] = ffma2(a3, w1, acc[3][1]);
      acc[0][2] = ffma2(a0, w2, acc[0][2]); acc[1][2] = ffma2(a1, w2, acc[1][2]);
      acc[2][2] = ffma2(a2, w2, acc[2][2]); acc[3][2] = ffma2(a3, w2, acc[3][2]);
      acc[0][3] = ffma2(a0, w3, acc[0][3]); acc[1][3] = ffma2(a1, w3, acc[1][3]);
      acc[2][3] = ffma2(a2, w3, acc[2][3]); acc[3][3] = ffma2(a3, w3, acc[3][3]);
      acc[0][4] = ffma2(a0, w4, acc[0][4]); acc[1][4] = ffma2(a1, w4, acc[1][4]);
      acc[2][4] = ffma2(a2, w4, acc[2][4]); acc[3][4] = ffma2(a3, w4, acc[3][4]);
      acc[0][5] = ffma2(a0, w5, acc[0][5]); acc[1][5] = ffma2(a1, w5, acc[1][5]);
      acc[2][5] = ffma2(a2, w5, acc[2][5]); acc[3][5] = ffma2(a3, w5, acc[3][5]);
      acc[0][6] = ffma2(a0, w6, acc[0][6]); acc[1][6] = ffma2(a1, w6, acc[1][6]);
      acc[2][6] = ffma2(a2, w6, acc[2][6]); acc[3][6] = ffma2(a3, w6, acc[3][6]);
      acc[0][7] = ffma2(a0, w7, acc[0][7]); acc[1][7] = ffma2(a1, w7, acc[1][7]);
      acc[2][7] = ffma2(a2, w7, acc[2][7]); acc[3][7] = ffma2(a3, w7, acc[3][7]);
    }
    // p = 1
    {
      ull a0 = fmul2(va.x, xp1[0]);
      ull a1 = fmul2(va.y, xp1[1]);
      ull a2 = fmul2(vb.x, xp1[2]);
      ull a3 = fmul2(vb.y, xp1[3]);
      const float* wrow = &ws[(1 * Dn + r) * WST + li * 8];
      float4 wA = *reinterpret_cast<const float4*>(wrow);
      float4 wB = *reinterpret_cast<const float4*>(wrow + 4);
      ull w0 = dup2(wA.x), w1 = dup2(wA.y), w2 = dup2(wA.z), w3 = dup2(wA.w);
      ull w4 = dup2(wB.x), w5 = dup2(wB.y), w6 = dup2(wB.z), w7 = dup2(wB.w);
      acc[0][0] = ffma2(a0, w0, acc[0][0]); acc[1][0] = ffma2(a1, w0, acc[1][0]);
      acc[2][0] = ffma2(a2, w0, acc[2][0]); acc[3][0] = ffma2(a3, w0, acc[3][0]);
      acc[0][1] = ffma2(a0, w1, acc[0][1]); acc[1][1] = ffma2(a1, w1, acc[1][1]);
      acc[2][1] = ffma2(a2, w1, acc[2][1]); acc[3][1] = ffma2(a3, w1, acc[3][1]);
      acc[0][2] = ffma2(a0, w2, acc[0][2]); acc[1][2] = ffma2(a1, w2, acc[1][2]);
      acc[2][2] = ffma2(a2, w2, acc[2][2]); acc[3][2] = ffma2(a3, w2, acc[3][2]);
      acc[0][3] = ffma2(a0, w3, acc[0][3]); acc[1][3] = ffma2(a1, w3, acc[1][3]);
      acc[2][3] = ffma2(a2, w3, acc[2][3]); acc[3][3] = ffma2(a3, w3, acc[3][3]);
      acc[0][4] = ffma2(a0, w4, acc[0][4]); acc[1][4] = ffma2(a1, w4, acc[1][4]);
      acc[2][4] = ffma2(a2, w4, acc[2][4]); acc[3][4] = ffma2(a3, w4, acc[3][4]);
      acc[0][5] = ffma2(a0, w5, acc[0][5]); acc[1][5] = ffma2(a1, w5, acc[1][5]);
      acc[2][5] = ffma2(a2, w5, acc[2][5]); acc[3][5] = ffma2(a3, w5, acc[3][5]);
      acc[0][6] = ffma2(a0, w6, acc[0][6]); acc[1][6] = ffma2(a1, w6, acc[1][6]);
      acc[2][6] = ffma2(a2, w6, acc[2][6]); acc[3][6] = ffma2(a3, w6, acc[3][6]);
      acc[0][7] = ffma2(a0, w7, acc[0][7]); acc[1][7] = ffma2(a1, w7, acc[1][7]);
      acc[2][7] = ffma2(a2, w7, acc[2][7]); acc[3][7] = ffma2(a3, w7, acc[3][7]);
    }
  }

  // store partials: g_part[ks][l][s]
  float* op = g_part + (size_t)blockIdx.y * (Bn * Dn);
#pragma unroll
  for (int q = 0; q < 8; ++q) {
    int l = li * 8 + q;
#pragma unroll
    for (int jj = 0; jj < 4; ++jj) {
      float a, b;
      unpack2(acc[jj][q], a, b);
      *reinterpret_cast<float2*>(&op[(size_t)l * Bn + s0 + si * 8 + 2 * jj]) =
          make_float2(a, b);
    }
  }
}

// g_v[i] = sum_ks partial[ks][i]  (both [l][s]-linear)
__global__ void reduce_v_kernel() {
  int i = blockIdx.x * blockDim.x + threadIdx.x;
  if (i < Bn * Dn) {
    float sv = 0.f;
#pragma unroll
    for (int k = 0; k < KS; ++k) sv += g_part[(size_t)k * Bn * Dn + i];
    g_v[i] = sv;
  }
}

// ---------------------------------------------------------------------------
// final: partial_out[ks][s,c] = sum_{p in chunk} sum_r cfirst[c,p,r]*x[s,0,p]*v[r,s]
// ---------------------------------------------------------------------------
__global__ __launch_bounds__(128) void final_kernel(const float* __restrict__ x,
                                                    const float* __restrict__ cfirst) {
  __shared__ __align__(16) float fs[Dn * 12];  // [r][c]
  const int tid = threadIdx.x;
  const int s = blockIdx.x * 128 + tid;
  const int pbase = blockIdx.y * PCF;

  float vr[Dn];
#pragma unroll
  for (int r = 0; r < Dn; ++r) vr[r] = g_v[(size_t)r * Bn + s];

  float xr[PCF];
  {
    const float4* xp =
        reinterpret_cast<const float4*>(x + (size_t)s * (Nn * Fn) + pbase);
#pragma unroll
    for (int k = 0; k < PCF / 4; ++k) {
      float4 t = xp[k];
      xr[4 * k] = t.x; xr[4 * k + 1] = t.y; xr[4 * k + 2] = t.z; xr[4 * k + 3] = t.w;
    }
  }

  ull acc[5];
#pragma unroll
  for (int q = 0; q < 5; ++q) acc[q] = 0ull;

#pragma unroll 1
  for (int pp = 0; pp < PCF; ++pp) {
    __syncthreads();
    {
      const float* cp = cfirst + (size_t)(pbase + pp) * Dn;
#pragma unroll
      for (int k = 0; k < 5; ++k) {
        int idx = k * 128 + tid;
        int r = idx & 63;
        int c = idx >> 6;
        fs[r * 12 + c] = cp[(size_t)c * (Fn * Dn) + r];
      }
    }
    __syncthreads();
    const float xpv = xr[pp];
#pragma unroll 8
    for (int r = 0; r < Dn; ++r) {
      ull t2 = dup2(xpv * vr[r]);
      const float* base = &fs[r * 12];
      ulonglong2 a01 = *reinterpret_cast<const ulonglong2*>(base);
      ulonglong2 a23 = *reinterpret_cast<const ulonglong2*>(base + 4);
      ull a4 = *reinterpret_cast<const ull*>(base + 8);
      acc[0] = ffma2(a01.x, t2, acc[0]);
      acc[1] = ffma2(a01.y, t2, acc[1]);
      acc[2] = ffma2(a23.x, t2, acc[2]);
      acc[3] = ffma2(a23.y, t2, acc[3]);
      acc[4] = ffma2(a4, t2, acc[4]);
    }
  }

  float o[10];
#pragma unroll
  for (int q = 0; q < 5; ++q) unpack2(acc[q], o[2 * q], o[2 * q + 1]);
  float* op = g_part + ((size_t)blockIdx.y * Bn + s) * 12;
  reinterpret_cast<float4*>(op)[0] = make_float4(o[0], o[1], o[2], o[3]);
  reinterpret_cast<float4*>(op)[1] = make_float4(o[4], o[5], o[6], o[7]);
  reinterpret_cast<float2*>(op + 8)[0] = make_float2(o[8], o[9]);
}

__global__ void reduce_out_kernel(float* __restrict__ out) {
  int i = blockIdx.x * blockDim.x + threadIdx.x;
  if (i < Bn * Cn) {
    int s = i / Cn;
    int c = i - s * Cn;
    float acc = 0.f;
#pragma unroll
    for (int k = 0; k < KSF; ++k) acc += g_part[((size_t)k * Bn + s) * 12 + c];
    out[i] = acc;
  }
}

}  // namespace

extern "C" void kernel_launch(void* const* d_in, const int* in_sizes, int n_in,
                              void* d_out, int out_size) {
  const float* x = (const float*)d_in[0];       // (4096, 8, 64)
  const float* cfirst = (const float*)d_in[1];  // (10, 64, 64)
  const float* cmid = (const float*)d_in[2];    // (6, 64, 64, 64)
  const float* clast = (const float*)d_in[3];   // (64, 64)
  float* out = (float*)d_out;                   // (4096, 10)

  static bool attr_done = false;
  if (!attr_done) {
    cudaFuncSetAttribute(mid_step_kernel,
                         cudaFuncAttributeMaxDynamicSharedMemorySize,
                         SM_MID_BYTES);
    attr_done = true;
  }

  preconv_w_kernel<<<NMID * Fn, 256>>>(cmid);
  init_v_kernel<<<Bn / 64, 256>>>(x, clast);

  for (int j = NMID - 1; j >= 0; --j) {
    mid_step_kernel<<<dim3(Bn / 128, KS), 128, SM_MID_BYTES>>>(x, j, j + 1);
    reduce_v_kernel<<<(Bn * Dn) / 256, 256>>>();
  }

  final_kernel<<<dim3(Bn / 128, KSF), 128>>>(x, cfirst);
  reduce_out_kernel<<<(Bn * Cn + 255) / 256, 256>>>(out);
}